// round 14
// baseline (speedup 1.0000x reference)
#include <cuda_runtime.h>
#include <cuda_fp16.h>
#include <math.h>
#include <stdint.h>

#define CS    8
#define KC    256
#define NH    16
#define D     64
#define CDIM  1024
#define MAXB  8
#define MAXLK 4096
#define MAXTOK (MAXB*MAXLK)

// ---------------- device scratch ----------------
__device__ int   g_idx[MAXTOK];
__device__ int   g_counts[MAXB*KC];
__device__ float g_codv[MAXB*KC*CDIM];          // [b][bucket][C]  8 MB

// ---------------- helpers ----------------
__device__ __forceinline__ uint32_t pack_h2(float a, float b) {
    __half2 h = __floats2half2_rn(a, b);
    return *(uint32_t*)&h;
}
__device__ __forceinline__ uint32_t hadd2_u(uint32_t a, uint32_t b) {
    __half2 r = __hadd2(*(__half2*)&a, *(__half2*)&b);
    return *(uint32_t*)&r;
}
__device__ __forceinline__ uint32_t ex2_h2(uint32_t x) {
    uint32_t r; asm("ex2.approx.f16x2 %0, %1;" : "=r"(r) : "r"(x)); return r;
}
__device__ __forceinline__ uint32_t prmt_u(uint32_t a, uint32_t b, uint32_t sel) {
    uint32_t r; asm("prmt.b32 %0, %1, %2, %3;" : "=r"(r) : "r"(a), "r"(b), "r"(sel));
    return r;
}
__device__ __forceinline__ void mma_f16(float c[4], const uint32_t a[4],
                                        uint32_t b0, uint32_t b1) {
    asm volatile("mma.sync.aligned.m16n8k16.row.col.f32.f16.f16.f32 "
        "{%0,%1,%2,%3}, {%4,%5,%6,%7}, {%8,%9}, {%0,%1,%2,%3};"
        : "+f"(c[0]), "+f"(c[1]), "+f"(c[2]), "+f"(c[3])
        : "r"(a[0]), "r"(a[1]), "r"(a[2]), "r"(a[3]), "r"(b0), "r"(b1));
}

// ---------------- K0: zero counts ----------------
__global__ void zero_counts_kernel(int n) {
    int i = blockIdx.x * blockDim.x + threadIdx.x;
    if (i < n) g_counts[i] = 0;
}

// ---------------- K1: bucket index + histogram (W hoisted, 8 rows/iter) ----------------
__global__ void __launch_bounds__(256) idx_kernel(
    const float* __restrict__ k, const float* __restrict__ Wc,
    const float* __restrict__ bc, int Lk, int nTok)
{
    __shared__ float4 sW[CS * (CDIM/4)];   // 32 KB
    __shared__ float  sbc[CS];
    int t = threadIdx.x;
    for (int i = t; i < CS * (CDIM/4); i += 256) sW[i] = ((const float4*)Wc)[i];
    if (t < CS) sbc[t] = bc[t];
    __syncthreads();

    int warp = t >> 5, lane = t & 31;
    int rowBase = (blockIdx.x * 8 + warp) * 8;
    if (rowBase >= nTok) return;
    const float4* kbase = (const float4*)(k + (size_t)rowBase * CDIM);

    float acc[8][8];
    #pragma unroll
    for (int r = 0; r < 8; r++)
        #pragma unroll
        for (int j = 0; j < CS; j++) acc[r][j] = 0.f;

    for (int i = lane; i < CDIM/4; i += 32) {
        float4 wv[8];
        #pragma unroll
        for (int j = 0; j < CS; j++) wv[j] = sW[j * (CDIM/4) + i];
        #pragma unroll
        for (int r = 0; r < 8; r++) {
            float4 kv = kbase[(size_t)r * (CDIM/4) + i];
            #pragma unroll
            for (int j = 0; j < CS; j++)
                acc[r][j] += kv.x*wv[j].x + kv.y*wv[j].y + kv.z*wv[j].z + kv.w*wv[j].w;
        }
    }
    #pragma unroll
    for (int r = 0; r < 8; r++) {
        #pragma unroll
        for (int j = 0; j < CS; j++) {
            #pragma unroll
            for (int o = 16; o >= 1; o >>= 1)
                acc[r][j] += __shfl_xor_sync(0xffffffffu, acc[r][j], o);
        }
        if (lane == 0) {
            int rr = rowBase + r;
            int code = 0;
            #pragma unroll
            for (int j = 0; j < CS; j++)
                if (acc[r][j] + sbc[j] >= 0.f) code |= (1 << (7 - j));
            g_idx[rr] = code;
            int b = rr / Lk;
            atomicAdd(&g_counts[b * KC + code], 1);
        }
    }
}

// ---------------- K5: gather-sum v per bucket (ballot-compaction, 4-way MLP) ----
// One block per (b, bucket). Scans the batch's g_idx slice (L2-hot, 16KB/batch)
// and builds the token list in ascending order via ballot prefix compaction --
// identical ordering to the old scan+scatter+sort path, so fp sums are bitwise
// identical. toks holds BATCH-LOCAL indices; v is re-based per batch (R13 bug fix).
__global__ void __launch_bounds__(256) gather_kernel(const float* __restrict__ v, int Lk) {
    int bk = blockIdx.x;
    int b = bk >> 8, bucket = bk & (KC - 1);
    __shared__ int toks[MAXLK];      // 16 KB, covers worst case cnt == Lk
    __shared__ int s_base[9];
    int t = threadIdx.x, warp = t >> 5, lane = t & 31;
    const int* idxb = g_idx + (size_t)b * Lk;
    const float* vb = v + (size_t)b * Lk * CDIM;   // batch base (the fix)
    int cnt = 0;

    for (int base = 0; base < Lk; base += 256) {
        int id = idxb[base + t];
        bool m = (id == bucket);
        unsigned bal = __ballot_sync(0xffffffffu, m);
        if (lane == 0) s_base[warp] = __popc(bal);
        __syncthreads();
        if (t == 0) {
            int acc = cnt;
            #pragma unroll
            for (int wq = 0; wq < 8; wq++) {
                int c = s_base[wq]; s_base[wq] = acc; acc += c;
            }
            s_base[8] = acc;
        }
        __syncthreads();
        if (m) {
            int pos = s_base[warp] + __popc(bal & ((1u << lane) - 1u));
            toks[pos] = base + t;
        }
        cnt = s_base[8];
        __syncthreads();
    }

    float4 a0 = make_float4(0.f,0.f,0.f,0.f), a1 = a0, a2 = a0, a3 = a0;
    int i = 0;
    for (; i + 4 <= cnt; i += 4) {
        float4 x0 = *(const float4*)(vb + (size_t)toks[i]     * CDIM + t * 4);
        float4 x1 = *(const float4*)(vb + (size_t)toks[i + 1] * CDIM + t * 4);
        float4 x2 = *(const float4*)(vb + (size_t)toks[i + 2] * CDIM + t * 4);
        float4 x3 = *(const float4*)(vb + (size_t)toks[i + 3] * CDIM + t * 4);
        a0.x += x0.x; a0.y += x0.y; a0.z += x0.z; a0.w += x0.w;
        a1.x += x1.x; a1.y += x1.y; a1.z += x1.z; a1.w += x1.w;
        a2.x += x2.x; a2.y += x2.y; a2.z += x2.z; a2.w += x2.w;
        a3.x += x3.x; a3.y += x3.y; a3.z += x3.z; a3.w += x3.w;
    }
    for (; i < cnt; i++) {
        float4 x0 = *(const float4*)(vb + (size_t)toks[i] * CDIM + t * 4);
        a0.x += x0.x; a0.y += x0.y; a0.z += x0.z; a0.w += x0.w;
    }
    float4 acc;
    acc.x = (a0.x + a1.x) + (a2.x + a3.x);
    acc.y = (a0.y + a1.y) + (a2.y + a3.y);
    acc.z = (a0.z + a1.z) + (a2.z + a3.z);
    acc.w = (a0.w + a1.w) + (a2.w + a3.w);
    *(float4*)(g_codv + (size_t)bk * CDIM + t * 4) = acc;
}

// ---------------- K6: low-rank fp16 attention, 512 threads, M=32/warp ----------------
// grid(NH, B) = 128 CTAs, 1 CTA/SM, 16 warps (4/SMSP). q-tile = 512 rows.
// A-frags for both m16 blocks computed sequentially (reg-lean), then ONE shared
// V-fragment loop feeds both blocks' PV MMAs (halves chunk LDS vs R12).
#define NTHREADS 512
#define CB_OFF  0
#define BA_OFF  3072
#define V_OFF   11264
#define CNT_OFF 54272
#define MSK_OFF 55296
#define VST_OFF 55808
#define SM_TOT  (VST_OFF + KC*D*2)     // 88576

__global__ void __launch_bounds__(NTHREADS, 1) attn_kernel(
    const float* __restrict__ q, const float* __restrict__ cb,
    float* __restrict__ out, int Lq)
{
    extern __shared__ char sm[];
    uint32_t* Cbs  = (uint32_t*)(sm + CB_OFF);
    uint2*    BA2  = (uint2*)   (sm + BA_OFF);
    uint32_t* Vsm  = (uint32_t*)(sm + V_OFF);
    float*    cntS = (float*)   (sm + CNT_OFF);
    uint32_t* mskS = (uint32_t*)(sm + MSK_OFF);
    uint32_t* Vst  = (uint32_t*)(sm + VST_OFF);   // half2[256*32]

    const int t = threadIdx.x, lane = t & 31, w = t >> 5;
    const int h = blockIdx.x, b = blockIdx.y;
    const int j = lane & 3, g = lane >> 2;
    const float QS = 0.125f * 1.4426950408889634f;   // scale * log2(e)

    // ---- Phase A: cb frags (QS folded), base frags, zero V slot-4,
    //      fp16-stage cod_v slice, counts ----
    {
        int s = t;                         // 512 float2, one per thread
        int n = s >> 5, p = s & 31;
        const float* src = cb + (size_t)n * CDIM + h * D + 2 * p;
        float2 x = make_float2(src[0] * QS, src[1] * QS);
        int jj = p & 3, qq = p >> 2;
        int kc = qq >> 1, ww = qq & 1;
        int slot = kc >> 1, c = ((kc & 1) << 1) | ww;
        Cbs[((n*4 + jj)*3 + slot)*4 + c] = pack_h2(x.x, x.y);
    }
    #pragma unroll
    for (int i = 0; i < 2; i++) {
        int s = t + NTHREADS * i;          // 1024 : bucket n, jj
        int n = s >> 2, jj = s & 3;
        float b0a = (float)((n >> (7 - 2*jj)) & 1);
        float b0b = (float)((n >> (7 - (2*jj+1))) & 1);
        BA2[n*4 + jj] = make_uint2(pack_h2(b0a, b0b),
                                   pack_h2(1.f - b0a, 1.f - b0b));
    }
    {
        int i = t;                         // 512 slot-4 entries, one per thread
        int row = i >> 3, gg = i & 7;
        uint32_t* p4 = &Vsm[(row*42 + gg*5 + 4)*4];
        p4[0] = 0; p4[1] = 0; p4[2] = 0; p4[3] = 0;
    }
    {   // stage cod_v (b,h) slice as fp16: Vst half2 index n*32 + d2
        const float4* vsrc = (const float4*)(g_codv + ((size_t)b * KC) * CDIM + h * D);
        uint2* vst2 = (uint2*)Vst;
        #pragma unroll
        for (int i = 0; i < 8; i++) {
            int s = t + NTHREADS * i;      // 4096 float4
            int n = s >> 4, c4 = s & 15;
            float4 x = vsrc[(size_t)n * (CDIM/4) + c4];
            vst2[n * 16 + c4] = make_uint2(pack_h2(x.x, x.y), pack_h2(x.z, x.w));
        }
    }
    if (t < KC) cntS[t] = (float)g_counts[b * KC + t];
    __syncthreads();

    // ---- Phase B: pack V^T frags from fp16 staging (PRMT repack),
    //      counts column, masks ----
    #pragma unroll
    for (int i = 0; i < 8; i++) {
        int s = t + NTHREADS * i;          // 4096 : d2 pair x bucket pair
        int d2 = s & 31, p = s >> 5;       // p = bucket pair 0..127
        uint32_t a  = Vst[(2*p)     * 32 + d2];
        uint32_t b2 = Vst[(2*p + 1) * 32 + d2];
        uint32_t lo = prmt_u(a, b2, 0x5410);   // {a.h0, b.h0}
        uint32_t hi = prmt_u(a, b2, 0x7632);   // {a.h1, b.h1}
        int ch = p >> 3, r = p & 7;
        int jj = r & 3, ww = r >> 2;
        #pragma unroll
        for (int e = 0; e < 2; e++) {
            int d = 2*d2 + e;
            uint32_t val = e ? hi : lo;
            int nbk = d >> 3, gg = d & 7;
            int slot = nbk >> 1, c = ((nbk & 1) << 1) | ww;
            Vsm[(((ch*4 + jj)*42) + gg*5 + slot)*4 + c] = val;
        }
    }
    if (t < 64) {                          // counts column at dim col 64 (g=0)
        int ch = t >> 2, jj = t & 3;
        uint32_t* p4 = &Vsm[(t*42 + 4)*4];
        p4[0] = pack_h2(cntS[ch*16 + 2*jj],     cntS[ch*16 + 2*jj + 1]);
        p4[1] = pack_h2(cntS[ch*16 + 8 + 2*jj], cntS[ch*16 + 8 + 2*jj + 1]);
    }
    if (t < KC/2) {
        uint32_t m = 0;
        if (!(cntS[2*t]     > 0.f)) m |= 0xFC00u;
        if (!(cntS[2*t + 1] > 0.f)) m |= 0xFC00u << 16;
        mskS[t] = m;
    }
    __syncthreads();

    const uint4* CB4 = (const uint4*)Cbs;
    const uint4* VB  = (const uint4*)Vsm;

    for (int q0 = 0; q0 < Lq; q0 += NTHREADS) {
        // cb B-frags reloaded per tile (not live in hot loop)
        uint4 cbA0 = CB4[(g*4 + j)*3 + 0];
        uint4 cbA1 = CB4[(g*4 + j)*3 + 1];
        uint4 cbB0 = CB4[((8+g)*4 + j)*3 + 0];
        uint4 cbB1 = CB4[((8+g)*4 + j)*3 + 1];

        // ---- T = Q @ cb^T for two m16 blocks; C-frag -> A-frag ----
        uint32_t AT0[4], AT1[4];
        {
            const float* qr0 = q + (size_t)(b * Lq + q0 + w * 32 + g) * CDIM + h * D;
            const float* qr8 = qr0 + 8 * CDIM;
            uint32_t qa[4][4];
            #pragma unroll
            for (int kc = 0; kc < 4; kc++) {
                float2 x0 = *(const float2*)(qr0 + kc*16 + 2*j);
                float2 x1 = *(const float2*)(qr8 + kc*16 + 2*j);
                float2 x2 = *(const float2*)(qr0 + kc*16 + 8 + 2*j);
                float2 x3 = *(const float2*)(qr8 + kc*16 + 8 + 2*j);
                qa[kc][0] = pack_h2(x0.x, x0.y);
                qa[kc][1] = pack_h2(x1.x, x1.y);
                qa[kc][2] = pack_h2(x2.x, x2.y);
                qa[kc][3] = pack_h2(x3.x, x3.y);
            }
            float Tlo[4] = {0.f,0.f,0.f,0.f}, Thi[4] = {0.f,0.f,0.f,0.f};
            mma_f16(Tlo, qa[0], cbA0.x, cbA0.y);
            mma_f16(Tlo, qa[1], cbA0.z, cbA0.w);
            mma_f16(Tlo, qa[2], cbA1.x, cbA1.y);
            mma_f16(Tlo, qa[3], cbA1.z, cbA1.w);
            mma_f16(Thi, qa[0], cbB0.x, cbB0.y);
            mma_f16(Thi, qa[1], cbB0.z, cbB0.w);
            mma_f16(Thi, qa[2], cbB1.x, cbB1.y);
            mma_f16(Thi, qa[3], cbB1.z, cbB1.w);
            AT0[0] = pack_h2(Tlo[0], Tlo[1]);
            AT0[1] = pack_h2(Tlo[2], Tlo[3]);
            AT0[2] = pack_h2(Thi[0], Thi[1]);
            AT0[3] = pack_h2(Thi[2], Thi[3]);
        }
        {
            const float* qr16 = q + (size_t)(b * Lq + q0 + w * 32 + 16 + g) * CDIM + h * D;
            const float* qr24 = qr16 + 8 * CDIM;
            uint32_t qa[4][4];
            #pragma unroll
            for (int kc = 0; kc < 4; kc++) {
                float2 x0 = *(const float2*)(qr16 + kc*16 + 2*j);
                float2 x1 = *(const float2*)(qr24 + kc*16 + 2*j);
                float2 x2 = *(const float2*)(qr16 + kc*16 + 8 + 2*j);
                float2 x3 = *(const float2*)(qr24 + kc*16 + 8 + 2*j);
                qa[kc][0] = pack_h2(x0.x, x0.y);
                qa[kc][1] = pack_h2(x1.x, x1.y);
                qa[kc][2] = pack_h2(x2.x, x2.y);
                qa[kc][3] = pack_h2(x3.x, x3.y);
            }
            float Tlo[4] = {0.f,0.f,0.f,0.f}, Thi[4] = {0.f,0.f,0.f,0.f};
            mma_f16(Tlo, qa[0], cbA0.x, cbA0.y);
            mma_f16(Tlo, qa[1], cbA0.z, cbA0.w);
            mma_f16(Tlo, qa[2], cbA1.x, cbA1.y);
            mma_f16(Tlo, qa[3], cbA1.z, cbA1.w);
            mma_f16(Thi, qa[0], cbB0.x, cbB0.y);
            mma_f16(Thi, qa[1], cbB0.z, cbB0.w);
            mma_f16(Thi, qa[2], cbB1.x, cbB1.y);
            mma_f16(Thi, qa[3], cbB1.z, cbB1.w);
            AT1[0] = pack_h2(Tlo[0], Tlo[1]);
            AT1[1] = pack_h2(Tlo[2], Tlo[3]);
            AT1[2] = pack_h2(Thi[0], Thi[1]);
            AT1[3] = pack_h2(Thi[2], Thi[3]);
        }

        float O0[8][4], O1[8][4];
        #pragma unroll
        for (int nb = 0; nb < 8; nb++) {
            O0[nb][0]=0.f; O0[nb][1]=0.f; O0[nb][2]=0.f; O0[nb][3]=0.f;
            O1[nb][0]=0.f; O1[nb][1]=0.f; O1[nb][2]=0.f; O1[nb][3]=0.f;
        }
        float O8a[4] = {0.f,0.f,0.f,0.f}, O8b[4] = {0.f,0.f,0.f,0.f};

        #pragma unroll 2
        for (int ch = 0; ch < 16; ch++) {
            uint2 ba = BA2[(ch*16 + g)*4 + j];
            uint2 bb = BA2[(ch*16 + 8 + g)*4 + j];
            uint32_t mlo = mskS[ch*8 + j], mhi = mskS[ch*8 + 4 + j];

            // ---- A0: S(log2) + ex2 for block 0 ----
            uint32_t A0[4];
            {
                float slo[4] = {0.f,0.f,0.f,0.f}, shi[4] = {0.f,0.f,0.f,0.f};
                mma_f16(slo, AT0, ba.x, ba.y);
                mma_f16(shi, AT0, bb.x, bb.y);
                A0[0] = ex2_h2(hadd2_u(pack_h2(slo[0], slo[1]), mlo));
                A0[1] = ex2_h2(hadd2_u(pack_h2(slo[2], slo[3]), mlo));
                A0[2] = ex2_h2(hadd2_u(pack_h2(shi[0], shi[1]), mhi));
                A0[3] = ex2_h2(hadd2_u(pack_h2(shi[2], shi[3]), mhi));
            }
            // ---- A1: S(log2) + ex2 for block 1 ----
            uint32_t A1[4];
            {
                float slo[4] = {0.f,0.f,0.f,0.f}, shi[4] = {0.f,0.f,0.f,0.f};
                mma_f16(slo, AT1, ba.x, ba.y);
                mma_f16(shi, AT1, bb.x, bb.y);
                A1[0] = ex2_h2(hadd2_u(pack_h2(slo[0], slo[1]), mlo));
                A1[1] = ex2_h2(hadd2_u(pack_h2(slo[2], slo[3]), mlo));
                A1[2] = ex2_h2(hadd2_u(pack_h2(shi[0], shi[1]), mhi));
                A1[3] = ex2_h2(hadd2_u(pack_h2(shi[2], shi[3]), mhi));
            }

            // ---- shared V fragments feed both blocks ----
            const uint4* vrow = VB + (ch*4 + j)*42 + g*5;
            #pragma unroll
            for (int s = 0; s < 4; s++) {
                uint4 vv = vrow[s];
                mma_f16(O0[2*s],     A0, vv.x, vv.y);
                mma_f16(O0[2*s + 1], A0, vv.z, vv.w);
                mma_f16(O1[2*s],     A1, vv.x, vv.y);
                mma_f16(O1[2*s + 1], A1, vv.z, vv.w);
            }
            uint2 vc = *(const uint2*)(vrow + 4);
            mma_f16(O8a, A0, vc.x, vc.y);
            mma_f16(O8b, A1, vc.x, vc.y);
        }

        // ---- den at col 64 (j=0 lanes), broadcast within quad ----
        int src = lane & 28;
        float d00 = __shfl_sync(0xffffffffu, O8a[0], src);
        float d01 = __shfl_sync(0xffffffffu, O8a[2], src);
        float d10 = __shfl_sync(0xffffffffu, O8b[0], src);
        float d11 = __shfl_sync(0xffffffffu, O8b[2], src);
        float i00 = 1.0f / d00, i01 = 1.0f / d01;
        float i10 = 1.0f / d10, i11 = 1.0f / d11;

        // ---- epilogue: two blocks ----
        float* ob0  = out + (size_t)(b * Lq + q0 + w * 32 + g) * CDIM + h * D;
        float* ob8  = ob0 + 8  * CDIM;
        float* ob16 = ob0 + 16 * CDIM;
        float* ob24 = ob0 + 24 * CDIM;
        #pragma unroll
        for (int nbk = 0; nbk < 8; nbk++) {
            *(float2*)(ob0  + nbk*8 + 2*j) = make_float2(O0[nbk][0]*i00, O0[nbk][1]*i00);
            *(float2*)(ob8  + nbk*8 + 2*j) = make_float2(O0[nbk][2]*i01, O0[nbk][3]*i01);
            *(float2*)(ob16 + nbk*8 + 2*j) = make_float2(O1[nbk][0]*i10, O1[nbk][1]*i10);
            *(float2*)(ob24 + nbk*8 + 2*j) = make_float2(O1[nbk][2]*i11, O1[nbk][3]*i11);
        }
    }
}

// ---------------- launch ----------------
extern "C" void kernel_launch(void* const* d_in, const int* in_sizes, int n_in,
                              void* d_out, int out_size)
{
    const float* q  = (const float*)d_in[0];
    const float* k  = (const float*)d_in[1];
    const float* v  = (const float*)d_in[2];
    const float* Wc = (const float*)d_in[3];
    const float* bc = (const float*)d_in[4];
    const float* cb = (const float*)d_in[5];

    int B    = in_sizes[6];
    int C    = in_sizes[3] / CS;
    int Lk   = in_sizes[1] / (B * C);
    int Lq   = in_sizes[0] / (B * C);
    int nTok = B * Lk;
    (void)n_in; (void)out_size;

    zero_counts_kernel<<<(B * KC + 255) / 256, 256>>>(B * KC);
    idx_kernel<<<(nTok + 63) / 64, 256>>>(k, Wc, bc, Lk, nTok);
    gather_kernel<<<B * KC, 256>>>(v, Lk);

    cudaFuncSetAttribute(attn_kernel,
                         cudaFuncAttributeMaxDynamicSharedMemorySize, SM_TOT);
    dim3 grid(NH, B);
    attn_kernel<<<grid, NTHREADS, SM_TOT>>>(q, cb, (float*)d_out, Lq);
}

// round 15
// speedup vs baseline: 1.0794x; 1.0794x over previous
#include <cuda_runtime.h>
#include <cuda_fp16.h>
#include <math.h>
#include <stdint.h>

#define CS    8
#define KC    256
#define NH    16
#define D     64
#define CDIM  1024
#define MAXB  8
#define MAXLK 4096
#define MAXTOK (MAXB*MAXLK)

// ---------------- device scratch ----------------
__device__ int   g_idx[MAXTOK];
__device__ int   g_counts[MAXB*KC];
__device__ float g_codv[MAXB*KC*CDIM];          // [b][bucket][C]  8 MB

// ---------------- helpers ----------------
__device__ __forceinline__ uint32_t pack_h2(float a, float b) {
    __half2 h = __floats2half2_rn(a, b);
    return *(uint32_t*)&h;
}
__device__ __forceinline__ uint32_t hadd2_u(uint32_t a, uint32_t b) {
    __half2 r = __hadd2(*(__half2*)&a, *(__half2*)&b);
    return *(uint32_t*)&r;
}
__device__ __forceinline__ uint32_t ex2_h2(uint32_t x) {
    uint32_t r; asm("ex2.approx.f16x2 %0, %1;" : "=r"(r) : "r"(x)); return r;
}
__device__ __forceinline__ uint32_t prmt_u(uint32_t a, uint32_t b, uint32_t sel) {
    uint32_t r; asm("prmt.b32 %0, %1, %2, %3;" : "=r"(r) : "r"(a), "r"(b), "r"(sel));
    return r;
}
__device__ __forceinline__ void mma_f16(float c[4], const uint32_t a[4],
                                        uint32_t b0, uint32_t b1) {
    asm volatile("mma.sync.aligned.m16n8k16.row.col.f32.f16.f16.f32 "
        "{%0,%1,%2,%3}, {%4,%5,%6,%7}, {%8,%9}, {%0,%1,%2,%3};"
        : "+f"(c[0]), "+f"(c[1]), "+f"(c[2]), "+f"(c[3])
        : "r"(a[0]), "r"(a[1]), "r"(a[2]), "r"(a[3]), "r"(b0), "r"(b1));
}

// ---------------- K1: bucket index (W hoisted, 8 rows/iter, no atomics) ----------------
__global__ void __launch_bounds__(256) idx_kernel(
    const float* __restrict__ k, const float* __restrict__ Wc,
    const float* __restrict__ bc, int Lk, int nTok)
{
    __shared__ float4 sW[CS * (CDIM/4)];   // 32 KB
    __shared__ float  sbc[CS];
    int t = threadIdx.x;
    for (int i = t; i < CS * (CDIM/4); i += 256) sW[i] = ((const float4*)Wc)[i];
    if (t < CS) sbc[t] = bc[t];
    __syncthreads();

    int warp = t >> 5, lane = t & 31;
    int rowBase = (blockIdx.x * 8 + warp) * 8;
    if (rowBase >= nTok) return;
    const float4* kbase = (const float4*)(k + (size_t)rowBase * CDIM);

    float acc[8][8];
    #pragma unroll
    for (int r = 0; r < 8; r++)
        #pragma unroll
        for (int j = 0; j < CS; j++) acc[r][j] = 0.f;

    for (int i = lane; i < CDIM/4; i += 32) {
        float4 wv[8];
        #pragma unroll
        for (int j = 0; j < CS; j++) wv[j] = sW[j * (CDIM/4) + i];
        #pragma unroll
        for (int r = 0; r < 8; r++) {
            float4 kv = kbase[(size_t)r * (CDIM/4) + i];
            #pragma unroll
            for (int j = 0; j < CS; j++)
                acc[r][j] += kv.x*wv[j].x + kv.y*wv[j].y + kv.z*wv[j].z + kv.w*wv[j].w;
        }
    }
    #pragma unroll
    for (int r = 0; r < 8; r++) {
        #pragma unroll
        for (int j = 0; j < CS; j++) {
            #pragma unroll
            for (int o = 16; o >= 1; o >>= 1)
                acc[r][j] += __shfl_xor_sync(0xffffffffu, acc[r][j], o);
        }
        if (lane == 0) {
            int code = 0;
            #pragma unroll
            for (int j = 0; j < CS; j++)
                if (acc[r][j] + sbc[j] >= 0.f) code |= (1 << (7 - j));
            g_idx[rowBase + r] = code;
        }
    }
}

// ---------------- K5: gather-sum v per bucket (warp-local 2-pass compaction) ----
// One block per (b, bucket). Each warp owns a contiguous 512-token segment:
// pass 1 caches ballot masks in registers + per-warp count; single sync;
// pass 2 replays cached ballots into ascending positions. Ordering identical to
// the old sorted list -> bitwise-identical fp sums. Also writes g_counts
// (replacing zero_counts + idx atomics).
__global__ void __launch_bounds__(256) gather_kernel(const float* __restrict__ v, int Lk) {
    int bk = blockIdx.x;
    int b = bk >> 8, bucket = bk & (KC - 1);
    __shared__ int toks[MAXLK];      // 16 KB worst case
    __shared__ int wcnt[8];
    int t = threadIdx.x, warp = t >> 5, lane = t & 31;
    const int* idxb = g_idx + (size_t)b * Lk;
    const float* vb = v + (size_t)b * Lk * CDIM;

    // pass 1: ballots over this warp's segment (Lk/8 tokens, <= 16 iters)
    const int segLen = Lk >> 3;           // 512
    const int seg = warp * segLen;
    const int nIt = segLen >> 5;          // 16
    unsigned bals[MAXLK/8/32];
    int myCnt = 0;
    for (int it = 0; it < nIt; it++) {
        bool m = (idxb[seg + it*32 + lane] == bucket);
        unsigned bal = __ballot_sync(0xffffffffu, m);
        bals[it] = bal;
        myCnt += __popc(bal);
    }
    if (lane == 0) wcnt[warp] = myCnt;
    __syncthreads();
    int off = 0, cnt = 0;
    #pragma unroll
    for (int ww = 0; ww < 8; ww++) {
        int c = wcnt[ww];
        if (ww < warp) off += c;
        cnt += c;
    }
    // pass 2: replay cached ballots, store ascending token indices
    const unsigned lm = (1u << lane) - 1u;
    for (int it = 0; it < nIt; it++) {
        unsigned bal = bals[it];
        if (bal & (1u << lane))
            toks[off + __popc(bal & lm)] = seg + it*32 + lane;
        off += __popc(bal);
    }
    __syncthreads();

    // accumulate v rows (4-way MLP, fixed combine tree)
    float4 a0 = make_float4(0.f,0.f,0.f,0.f), a1 = a0, a2 = a0, a3 = a0;
    int i = 0;
    for (; i + 4 <= cnt; i += 4) {
        float4 x0 = *(const float4*)(vb + (size_t)toks[i]     * CDIM + t * 4);
        float4 x1 = *(const float4*)(vb + (size_t)toks[i + 1] * CDIM + t * 4);
        float4 x2 = *(const float4*)(vb + (size_t)toks[i + 2] * CDIM + t * 4);
        float4 x3 = *(const float4*)(vb + (size_t)toks[i + 3] * CDIM + t * 4);
        a0.x += x0.x; a0.y += x0.y; a0.z += x0.z; a0.w += x0.w;
        a1.x += x1.x; a1.y += x1.y; a1.z += x1.z; a1.w += x1.w;
        a2.x += x2.x; a2.y += x2.y; a2.z += x2.z; a2.w += x2.w;
        a3.x += x3.x; a3.y += x3.y; a3.z += x3.z; a3.w += x3.w;
    }
    for (; i < cnt; i++) {
        float4 x0 = *(const float4*)(vb + (size_t)toks[i] * CDIM + t * 4);
        a0.x += x0.x; a0.y += x0.y; a0.z += x0.z; a0.w += x0.w;
    }
    float4 acc;
    acc.x = (a0.x + a1.x) + (a2.x + a3.x);
    acc.y = (a0.y + a1.y) + (a2.y + a3.y);
    acc.z = (a0.z + a1.z) + (a2.z + a3.z);
    acc.w = (a0.w + a1.w) + (a2.w + a3.w);
    *(float4*)(g_codv + (size_t)bk * CDIM + t * 4) = acc;
    if (t == 0) g_counts[bk] = cnt;
}

// ---------------- K6: low-rank fp16 attention, 512 threads, M=32/warp ----------------
// (unchanged from R14: 49.6us, tensor 41%, ~85% of its HMMA floor)
#define NTHREADS 512
#define CB_OFF  0
#define BA_OFF  3072
#define V_OFF   11264
#define CNT_OFF 54272
#define MSK_OFF 55296
#define VST_OFF 55808
#define SM_TOT  (VST_OFF + KC*D*2)     // 88576

__global__ void __launch_bounds__(NTHREADS, 1) attn_kernel(
    const float* __restrict__ q, const float* __restrict__ cb,
    float* __restrict__ out, int Lq)
{
    extern __shared__ char sm[];
    uint32_t* Cbs  = (uint32_t*)(sm + CB_OFF);
    uint2*    BA2  = (uint2*)   (sm + BA_OFF);
    uint32_t* Vsm  = (uint32_t*)(sm + V_OFF);
    float*    cntS = (float*)   (sm + CNT_OFF);
    uint32_t* mskS = (uint32_t*)(sm + MSK_OFF);
    uint32_t* Vst  = (uint32_t*)(sm + VST_OFF);   // half2[256*32]

    const int t = threadIdx.x, lane = t & 31, w = t >> 5;
    const int h = blockIdx.x, b = blockIdx.y;
    const int j = lane & 3, g = lane >> 2;
    const float QS = 0.125f * 1.4426950408889634f;   // scale * log2(e)

    // ---- Phase A ----
    {
        int s = t;
        int n = s >> 5, p = s & 31;
        const float* src = cb + (size_t)n * CDIM + h * D + 2 * p;
        float2 x = make_float2(src[0] * QS, src[1] * QS);
        int jj = p & 3, qq = p >> 2;
        int kc = qq >> 1, ww = qq & 1;
        int slot = kc >> 1, c = ((kc & 1) << 1) | ww;
        Cbs[((n*4 + jj)*3 + slot)*4 + c] = pack_h2(x.x, x.y);
    }
    #pragma unroll
    for (int i = 0; i < 2; i++) {
        int s = t + NTHREADS * i;
        int n = s >> 2, jj = s & 3;
        float b0a = (float)((n >> (7 - 2*jj)) & 1);
        float b0b = (float)((n >> (7 - (2*jj+1))) & 1);
        BA2[n*4 + jj] = make_uint2(pack_h2(b0a, b0b),
                                   pack_h2(1.f - b0a, 1.f - b0b));
    }
    {
        int i = t;
        int row = i >> 3, gg = i & 7;
        uint32_t* p4 = &Vsm[(row*42 + gg*5 + 4)*4];
        p4[0] = 0; p4[1] = 0; p4[2] = 0; p4[3] = 0;
    }
    {
        const float4* vsrc = (const float4*)(g_codv + ((size_t)b * KC) * CDIM + h * D);
        uint2* vst2 = (uint2*)Vst;
        #pragma unroll
        for (int i = 0; i < 8; i++) {
            int s = t + NTHREADS * i;
            int n = s >> 4, c4 = s & 15;
            float4 x = vsrc[(size_t)n * (CDIM/4) + c4];
            vst2[n * 16 + c4] = make_uint2(pack_h2(x.x, x.y), pack_h2(x.z, x.w));
        }
    }
    if (t < KC) cntS[t] = (float)g_counts[b * KC + t];
    __syncthreads();

    // ---- Phase B ----
    #pragma unroll
    for (int i = 0; i < 8; i++) {
        int s = t + NTHREADS * i;
        int d2 = s & 31, p = s >> 5;
        uint32_t a  = Vst[(2*p)     * 32 + d2];
        uint32_t b2 = Vst[(2*p + 1) * 32 + d2];
        uint32_t lo = prmt_u(a, b2, 0x5410);
        uint32_t hi = prmt_u(a, b2, 0x7632);
        int ch = p >> 3, r = p & 7;
        int jj = r & 3, ww = r >> 2;
        #pragma unroll
        for (int e = 0; e < 2; e++) {
            int d = 2*d2 + e;
            uint32_t val = e ? hi : lo;
            int nbk = d >> 3, gg = d & 7;
            int slot = nbk >> 1, c = ((nbk & 1) << 1) | ww;
            Vsm[(((ch*4 + jj)*42) + gg*5 + slot)*4 + c] = val;
        }
    }
    if (t < 64) {
        int ch = t >> 2, jj = t & 3;
        uint32_t* p4 = &Vsm[(t*42 + 4)*4];
        p4[0] = pack_h2(cntS[ch*16 + 2*jj],     cntS[ch*16 + 2*jj + 1]);
        p4[1] = pack_h2(cntS[ch*16 + 8 + 2*jj], cntS[ch*16 + 8 + 2*jj + 1]);
    }
    if (t < KC/2) {
        uint32_t m = 0;
        if (!(cntS[2*t]     > 0.f)) m |= 0xFC00u;
        if (!(cntS[2*t + 1] > 0.f)) m |= 0xFC00u << 16;
        mskS[t] = m;
    }
    __syncthreads();

    const uint4* CB4 = (const uint4*)Cbs;
    const uint4* VB  = (const uint4*)Vsm;

    for (int q0 = 0; q0 < Lq; q0 += NTHREADS) {
        uint4 cbA0 = CB4[(g*4 + j)*3 + 0];
        uint4 cbA1 = CB4[(g*4 + j)*3 + 1];
        uint4 cbB0 = CB4[((8+g)*4 + j)*3 + 0];
        uint4 cbB1 = CB4[((8+g)*4 + j)*3 + 1];

        uint32_t AT0[4], AT1[4];
        {
            const float* qr0 = q + (size_t)(b * Lq + q0 + w * 32 + g) * CDIM + h * D;
            const float* qr8 = qr0 + 8 * CDIM;
            uint32_t qa[4][4];
            #pragma unroll
            for (int kc = 0; kc < 4; kc++) {
                float2 x0 = *(const float2*)(qr0 + kc*16 + 2*j);
                float2 x1 = *(const float2*)(qr8 + kc*16 + 2*j);
                float2 x2 = *(const float2*)(qr0 + kc*16 + 8 + 2*j);
                float2 x3 = *(const float2*)(qr8 + kc*16 + 8 + 2*j);
                qa[kc][0] = pack_h2(x0.x, x0.y);
                qa[kc][1] = pack_h2(x1.x, x1.y);
                qa[kc][2] = pack_h2(x2.x, x2.y);
                qa[kc][3] = pack_h2(x3.x, x3.y);
            }
            float Tlo[4] = {0.f,0.f,0.f,0.f}, Thi[4] = {0.f,0.f,0.f,0.f};
            mma_f16(Tlo, qa[0], cbA0.x, cbA0.y);
            mma_f16(Tlo, qa[1], cbA0.z, cbA0.w);
            mma_f16(Tlo, qa[2], cbA1.x, cbA1.y);
            mma_f16(Tlo, qa[3], cbA1.z, cbA1.w);
            mma_f16(Thi, qa[0], cbB0.x, cbB0.y);
            mma_f16(Thi, qa[1], cbB0.z, cbB0.w);
            mma_f16(Thi, qa[2], cbB1.x, cbB1.y);
            mma_f16(Thi, qa[3], cbB1.z, cbB1.w);
            AT0[0] = pack_h2(Tlo[0], Tlo[1]);
            AT0[1] = pack_h2(Tlo[2], Tlo[3]);
            AT0[2] = pack_h2(Thi[0], Thi[1]);
            AT0[3] = pack_h2(Thi[2], Thi[3]);
        }
        {
            const float* qr16 = q + (size_t)(b * Lq + q0 + w * 32 + 16 + g) * CDIM + h * D;
            const float* qr24 = qr16 + 8 * CDIM;
            uint32_t qa[4][4];
            #pragma unroll
            for (int kc = 0; kc < 4; kc++) {
                float2 x0 = *(const float2*)(qr16 + kc*16 + 2*j);
                float2 x1 = *(const float2*)(qr24 + kc*16 + 2*j);
                float2 x2 = *(const float2*)(qr16 + kc*16 + 8 + 2*j);
                float2 x3 = *(const float2*)(qr24 + kc*16 + 8 + 2*j);
                qa[kc][0] = pack_h2(x0.x, x0.y);
                qa[kc][1] = pack_h2(x1.x, x1.y);
                qa[kc][2] = pack_h2(x2.x, x2.y);
                qa[kc][3] = pack_h2(x3.x, x3.y);
            }
            float Tlo[4] = {0.f,0.f,0.f,0.f}, Thi[4] = {0.f,0.f,0.f,0.f};
            mma_f16(Tlo, qa[0], cbA0.x, cbA0.y);
            mma_f16(Tlo, qa[1], cbA0.z, cbA0.w);
            mma_f16(Tlo, qa[2], cbA1.x, cbA1.y);
            mma_f16(Tlo, qa[3], cbA1.z, cbA1.w);
            mma_f16(Thi, qa[0], cbB0.x, cbB0.y);
            mma_f16(Thi, qa[1], cbB0.z, cbB0.w);
            mma_f16(Thi, qa[2], cbB1.x, cbB1.y);
            mma_f16(Thi, qa[3], cbB1.z, cbB1.w);
            AT1[0] = pack_h2(Tlo[0], Tlo[1]);
            AT1[1] = pack_h2(Tlo[2], Tlo[3]);
            AT1[2] = pack_h2(Thi[0], Thi[1]);
            AT1[3] = pack_h2(Thi[2], Thi[3]);
        }

        float O0[8][4], O1[8][4];
        #pragma unroll
        for (int nb = 0; nb < 8; nb++) {
            O0[nb][0]=0.f; O0[nb][1]=0.f; O0[nb][2]=0.f; O0[nb][3]=0.f;
            O1[nb][0]=0.f; O1[nb][1]=0.f; O1[nb][2]=0.f; O1[nb][3]=0.f;
        }
        float O8a[4] = {0.f,0.f,0.f,0.f}, O8b[4] = {0.f,0.f,0.f,0.f};

        #pragma unroll 2
        for (int ch = 0; ch < 16; ch++) {
            uint2 ba = BA2[(ch*16 + g)*4 + j];
            uint2 bb = BA2[(ch*16 + 8 + g)*4 + j];
            uint32_t mlo = mskS[ch*8 + j], mhi = mskS[ch*8 + 4 + j];

            uint32_t A0[4];
            {
                float slo[4] = {0.f,0.f,0.f,0.f}, shi[4] = {0.f,0.f,0.f,0.f};
                mma_f16(slo, AT0, ba.x, ba.y);
                mma_f16(shi, AT0, bb.x, bb.y);
                A0[0] = ex2_h2(hadd2_u(pack_h2(slo[0], slo[1]), mlo));
                A0[1] = ex2_h2(hadd2_u(pack_h2(slo[2], slo[3]), mlo));
                A0[2] = ex2_h2(hadd2_u(pack_h2(shi[0], shi[1]), mhi));
                A0[3] = ex2_h2(hadd2_u(pack_h2(shi[2], shi[3]), mhi));
            }
            uint32_t A1[4];
            {
                float slo[4] = {0.f,0.f,0.f,0.f}, shi[4] = {0.f,0.f,0.f,0.f};
                mma_f16(slo, AT1, ba.x, ba.y);
                mma_f16(shi, AT1, bb.x, bb.y);
                A1[0] = ex2_h2(hadd2_u(pack_h2(slo[0], slo[1]), mlo));
                A1[1] = ex2_h2(hadd2_u(pack_h2(slo[2], slo[3]), mlo));
                A1[2] = ex2_h2(hadd2_u(pack_h2(shi[0], shi[1]), mhi));
                A1[3] = ex2_h2(hadd2_u(pack_h2(shi[2], shi[3]), mhi));
            }

            const uint4* vrow = VB + (ch*4 + j)*42 + g*5;
            #pragma unroll
            for (int s = 0; s < 4; s++) {
                uint4 vv = vrow[s];
                mma_f16(O0[2*s],     A0, vv.x, vv.y);
                mma_f16(O0[2*s + 1], A0, vv.z, vv.w);
                mma_f16(O1[2*s],     A1, vv.x, vv.y);
                mma_f16(O1[2*s + 1], A1, vv.z, vv.w);
            }
            uint2 vc = *(const uint2*)(vrow + 4);
            mma_f16(O8a, A0, vc.x, vc.y);
            mma_f16(O8b, A1, vc.x, vc.y);
        }

        int src = lane & 28;
        float d00 = __shfl_sync(0xffffffffu, O8a[0], src);
        float d01 = __shfl_sync(0xffffffffu, O8a[2], src);
        float d10 = __shfl_sync(0xffffffffu, O8b[0], src);
        float d11 = __shfl_sync(0xffffffffu, O8b[2], src);
        float i00 = 1.0f / d00, i01 = 1.0f / d01;
        float i10 = 1.0f / d10, i11 = 1.0f / d11;

        float* ob0  = out + (size_t)(b * Lq + q0 + w * 32 + g) * CDIM + h * D;
        float* ob8  = ob0 + 8  * CDIM;
        float* ob16 = ob0 + 16 * CDIM;
        float* ob24 = ob0 + 24 * CDIM;
        #pragma unroll
        for (int nbk = 0; nbk < 8; nbk++) {
            *(float2*)(ob0  + nbk*8 + 2*j) = make_float2(O0[nbk][0]*i00, O0[nbk][1]*i00);
            *(float2*)(ob8  + nbk*8 + 2*j) = make_float2(O0[nbk][2]*i01, O0[nbk][3]*i01);
            *(float2*)(ob16 + nbk*8 + 2*j) = make_float2(O1[nbk][0]*i10, O1[nbk][1]*i10);
            *(float2*)(ob24 + nbk*8 + 2*j) = make_float2(O1[nbk][2]*i11, O1[nbk][3]*i11);
        }
    }
}

// ---------------- launch ----------------
extern "C" void kernel_launch(void* const* d_in, const int* in_sizes, int n_in,
                              void* d_out, int out_size)
{
    const float* q  = (const float*)d_in[0];
    const float* k  = (const float*)d_in[1];
    const float* v  = (const float*)d_in[2];
    const float* Wc = (const float*)d_in[3];
    const float* bc = (const float*)d_in[4];
    const float* cb = (const float*)d_in[5];

    int B    = in_sizes[6];
    int C    = in_sizes[3] / CS;
    int Lk   = in_sizes[1] / (B * C);
    int Lq   = in_sizes[0] / (B * C);
    int nTok = B * Lk;
    (void)n_in; (void)out_size;

    idx_kernel<<<(nTok + 63) / 64, 256>>>(k, Wc, bc, Lk, nTok);
    gather_kernel<<<B * KC, 256>>>(v, Lk);

    cudaFuncSetAttribute(attn_kernel,
                         cudaFuncAttributeMaxDynamicSharedMemorySize, SM_TOT);
    dim3 grid(NH, B);
    attn_kernel<<<grid, NTHREADS, SM_TOT>>>(q, cb, (float*)d_out, Lq);
}

// round 16
// speedup vs baseline: 1.0990x; 1.0182x over previous
#include <cuda_runtime.h>
#include <cuda_fp16.h>
#include <math.h>
#include <stdint.h>

#define CS    8
#define KC    256
#define NH    16
#define D     64
#define CDIM  1024
#define MAXB  8
#define MAXLK 4096
#define MAXTOK (MAXB*MAXLK)

// ---------------- device scratch ----------------
__device__ int   g_idx[MAXTOK];
__device__ int   g_counts[MAXB*KC];
__device__ float g_codv[MAXB*KC*CDIM];          // [b][bucket][C]  8 MB

// ---------------- helpers ----------------
__device__ __forceinline__ uint32_t pack_h2(float a, float b) {
    __half2 h = __floats2half2_rn(a, b);
    return *(uint32_t*)&h;
}
__device__ __forceinline__ uint32_t hadd2_u(uint32_t a, uint32_t b) {
    __half2 r = __hadd2(*(__half2*)&a, *(__half2*)&b);
    return *(uint32_t*)&r;
}
__device__ __forceinline__ uint32_t ex2_h2(uint32_t x) {
    uint32_t r; asm("ex2.approx.f16x2 %0, %1;" : "=r"(r) : "r"(x)); return r;
}
__device__ __forceinline__ uint32_t prmt_u(uint32_t a, uint32_t b, uint32_t sel) {
    uint32_t r; asm("prmt.b32 %0, %1, %2, %3;" : "=r"(r) : "r"(a), "r"(b), "r"(sel));
    return r;
}
__device__ __forceinline__ void mma_f16(float c[4], const uint32_t a[4],
                                        uint32_t b0, uint32_t b1) {
    asm volatile("mma.sync.aligned.m16n8k16.row.col.f32.f16.f16.f32 "
        "{%0,%1,%2,%3}, {%4,%5,%6,%7}, {%8,%9}, {%0,%1,%2,%3};"
        : "+f"(c[0]), "+f"(c[1]), "+f"(c[2]), "+f"(c[3])
        : "r"(a[0]), "r"(a[1]), "r"(a[2]), "r"(a[3]), "r"(b0), "r"(b1));
}

// ---------------- K1: bucket index (4 rows/warp, 3 CTAs/SM) ----------------
__global__ void __launch_bounds__(256, 3) idx_kernel(
    const float* __restrict__ k, const float* __restrict__ Wc,
    const float* __restrict__ bc, int Lk, int nTok)
{
    __shared__ float4 sW[CS * (CDIM/4)];   // 32 KB
    __shared__ float  sbc[CS];
    int t = threadIdx.x;
    for (int i = t; i < CS * (CDIM/4); i += 256) sW[i] = ((const float4*)Wc)[i];
    if (t < CS) sbc[t] = bc[t];
    __syncthreads();

    int warp = t >> 5, lane = t & 31;
    int rowBase = (blockIdx.x * 8 + warp) * 4;
    if (rowBase >= nTok) return;
    const float4* kbase = (const float4*)(k + (size_t)rowBase * CDIM);

    float acc[4][8];
    #pragma unroll
    for (int r = 0; r < 4; r++)
        #pragma unroll
        for (int j = 0; j < CS; j++) acc[r][j] = 0.f;

    for (int i = lane; i < CDIM/4; i += 32) {
        float4 kv[4];
        #pragma unroll
        for (int r = 0; r < 4; r++) kv[r] = kbase[(size_t)r * (CDIM/4) + i];
        #pragma unroll
        for (int j = 0; j < CS; j++) {
            float4 wv = sW[j * (CDIM/4) + i];
            #pragma unroll
            for (int r = 0; r < 4; r++)
                acc[r][j] += kv[r].x*wv.x + kv[r].y*wv.y + kv[r].z*wv.z + kv[r].w*wv.w;
        }
    }
    #pragma unroll
    for (int r = 0; r < 4; r++) {
        #pragma unroll
        for (int j = 0; j < CS; j++) {
            #pragma unroll
            for (int o = 16; o >= 1; o >>= 1)
                acc[r][j] += __shfl_xor_sync(0xffffffffu, acc[r][j], o);
        }
        if (lane == 0) {
            int code = 0;
            #pragma unroll
            for (int j = 0; j < CS; j++)
                if (acc[r][j] + sbc[j] >= 0.f) code |= (1 << (7 - j));
            g_idx[rowBase + r] = code;
        }
    }
}

// ---------------- K5: gather-sum v per bucket (warp-local 2-pass compaction) ----
__global__ void __launch_bounds__(256) gather_kernel(const float* __restrict__ v, int Lk) {
    int bk = blockIdx.x;
    int b = bk >> 8, bucket = bk & (KC - 1);
    __shared__ int toks[MAXLK];
    __shared__ int wcnt[8];
    int t = threadIdx.x, warp = t >> 5, lane = t & 31;
    const int* idxb = g_idx + (size_t)b * Lk;
    const float* vb = v + (size_t)b * Lk * CDIM;

    const int segLen = Lk >> 3;           // 512
    const int seg = warp * segLen;
    const int nIt = segLen >> 5;          // 16
    unsigned bals[MAXLK/8/32];
    int myCnt = 0;
    for (int it = 0; it < nIt; it++) {
        bool m = (idxb[seg + it*32 + lane] == bucket);
        unsigned bal = __ballot_sync(0xffffffffu, m);
        bals[it] = bal;
        myCnt += __popc(bal);
    }
    if (lane == 0) wcnt[warp] = myCnt;
    __syncthreads();
    int off = 0, cnt = 0;
    #pragma unroll
    for (int ww = 0; ww < 8; ww++) {
        int c = wcnt[ww];
        if (ww < warp) off += c;
        cnt += c;
    }
    const unsigned lm = (1u << lane) - 1u;
    for (int it = 0; it < nIt; it++) {
        unsigned bal = bals[it];
        if (bal & (1u << lane))
            toks[off + __popc(bal & lm)] = seg + it*32 + lane;
        off += __popc(bal);
    }
    __syncthreads();

    // accumulate v rows (8-way MLP, fixed combine tree)
    float4 a0 = make_float4(0.f,0.f,0.f,0.f), a1 = a0, a2 = a0, a3 = a0;
    float4 a4 = a0, a5 = a0, a6 = a0, a7 = a0;
    int i = 0;
    for (; i + 8 <= cnt; i += 8) {
        float4 x0 = *(const float4*)(vb + (size_t)toks[i]     * CDIM + t * 4);
        float4 x1 = *(const float4*)(vb + (size_t)toks[i + 1] * CDIM + t * 4);
        float4 x2 = *(const float4*)(vb + (size_t)toks[i + 2] * CDIM + t * 4);
        float4 x3 = *(const float4*)(vb + (size_t)toks[i + 3] * CDIM + t * 4);
        float4 x4 = *(const float4*)(vb + (size_t)toks[i + 4] * CDIM + t * 4);
        float4 x5 = *(const float4*)(vb + (size_t)toks[i + 5] * CDIM + t * 4);
        float4 x6 = *(const float4*)(vb + (size_t)toks[i + 6] * CDIM + t * 4);
        float4 x7 = *(const float4*)(vb + (size_t)toks[i + 7] * CDIM + t * 4);
        a0.x += x0.x; a0.y += x0.y; a0.z += x0.z; a0.w += x0.w;
        a1.x += x1.x; a1.y += x1.y; a1.z += x1.z; a1.w += x1.w;
        a2.x += x2.x; a2.y += x2.y; a2.z += x2.z; a2.w += x2.w;
        a3.x += x3.x; a3.y += x3.y; a3.z += x3.z; a3.w += x3.w;
        a4.x += x4.x; a4.y += x4.y; a4.z += x4.z; a4.w += x4.w;
        a5.x += x5.x; a5.y += x5.y; a5.z += x5.z; a5.w += x5.w;
        a6.x += x6.x; a6.y += x6.y; a6.z += x6.z; a6.w += x6.w;
        a7.x += x7.x; a7.y += x7.y; a7.z += x7.z; a7.w += x7.w;
    }
    for (; i < cnt; i++) {
        float4 x0 = *(const float4*)(vb + (size_t)toks[i] * CDIM + t * 4);
        a0.x += x0.x; a0.y += x0.y; a0.z += x0.z; a0.w += x0.w;
    }
    float4 acc;
    acc.x = ((a0.x + a1.x) + (a2.x + a3.x)) + ((a4.x + a5.x) + (a6.x + a7.x));
    acc.y = ((a0.y + a1.y) + (a2.y + a3.y)) + ((a4.y + a5.y) + (a6.y + a7.y));
    acc.z = ((a0.z + a1.z) + (a2.z + a3.z)) + ((a4.z + a5.z) + (a6.z + a7.z));
    acc.w = ((a0.w + a1.w) + (a2.w + a3.w)) + ((a4.w + a5.w) + (a6.w + a7.w));
    *(float4*)(g_codv + (size_t)bk * CDIM + t * 4) = acc;
    if (t == 0) g_counts[bk] = cnt;
}

// ---------------- K6: low-rank fp16 attention, 512 threads, M=32/warp ----------------
// (unchanged from R15: 49.6us, ~85% of its HMMA floor)
#define NTHREADS 512
#define CB_OFF  0
#define BA_OFF  3072
#define V_OFF   11264
#define CNT_OFF 54272
#define MSK_OFF 55296
#define VST_OFF 55808
#define SM_TOT  (VST_OFF + KC*D*2)     // 88576

__global__ void __launch_bounds__(NTHREADS, 1) attn_kernel(
    const float* __restrict__ q, const float* __restrict__ cb,
    float* __restrict__ out, int Lq)
{
    extern __shared__ char sm[];
    uint32_t* Cbs  = (uint32_t*)(sm + CB_OFF);
    uint2*    BA2  = (uint2*)   (sm + BA_OFF);
    uint32_t* Vsm  = (uint32_t*)(sm + V_OFF);
    float*    cntS = (float*)   (sm + CNT_OFF);
    uint32_t* mskS = (uint32_t*)(sm + MSK_OFF);
    uint32_t* Vst  = (uint32_t*)(sm + VST_OFF);

    const int t = threadIdx.x, lane = t & 31, w = t >> 5;
    const int h = blockIdx.x, b = blockIdx.y;
    const int j = lane & 3, g = lane >> 2;
    const float QS = 0.125f * 1.4426950408889634f;

    {
        int s = t;
        int n = s >> 5, p = s & 31;
        const float* src = cb + (size_t)n * CDIM + h * D + 2 * p;
        float2 x = make_float2(src[0] * QS, src[1] * QS);
        int jj = p & 3, qq = p >> 2;
        int kc = qq >> 1, ww = qq & 1;
        int slot = kc >> 1, c = ((kc & 1) << 1) | ww;
        Cbs[((n*4 + jj)*3 + slot)*4 + c] = pack_h2(x.x, x.y);
    }
    #pragma unroll
    for (int i = 0; i < 2; i++) {
        int s = t + NTHREADS * i;
        int n = s >> 2, jj = s & 3;
        float b0a = (float)((n >> (7 - 2*jj)) & 1);
        float b0b = (float)((n >> (7 - (2*jj+1))) & 1);
        BA2[n*4 + jj] = make_uint2(pack_h2(b0a, b0b),
                                   pack_h2(1.f - b0a, 1.f - b0b));
    }
    {
        int i = t;
        int row = i >> 3, gg = i & 7;
        uint32_t* p4 = &Vsm[(row*42 + gg*5 + 4)*4];
        p4[0] = 0; p4[1] = 0; p4[2] = 0; p4[3] = 0;
    }
    {
        const float4* vsrc = (const float4*)(g_codv + ((size_t)b * KC) * CDIM + h * D);
        uint2* vst2 = (uint2*)Vst;
        #pragma unroll
        for (int i = 0; i < 8; i++) {
            int s = t + NTHREADS * i;
            int n = s >> 4, c4 = s & 15;
            float4 x = vsrc[(size_t)n * (CDIM/4) + c4];
            vst2[n * 16 + c4] = make_uint2(pack_h2(x.x, x.y), pack_h2(x.z, x.w));
        }
    }
    if (t < KC) cntS[t] = (float)g_counts[b * KC + t];
    __syncthreads();

    #pragma unroll
    for (int i = 0; i < 8; i++) {
        int s = t + NTHREADS * i;
        int d2 = s & 31, p = s >> 5;
        uint32_t a  = Vst[(2*p)     * 32 + d2];
        uint32_t b2 = Vst[(2*p + 1) * 32 + d2];
        uint32_t lo = prmt_u(a, b2, 0x5410);
        uint32_t hi = prmt_u(a, b2, 0x7632);
        int ch = p >> 3, r = p & 7;
        int jj = r & 3, ww = r >> 2;
        #pragma unroll
        for (int e = 0; e < 2; e++) {
            int d = 2*d2 + e;
            uint32_t val = e ? hi : lo;
            int nbk = d >> 3, gg = d & 7;
            int slot = nbk >> 1, c = ((nbk & 1) << 1) | ww;
            Vsm[(((ch*4 + jj)*42) + gg*5 + slot)*4 + c] = val;
        }
    }
    if (t < 64) {
        int ch = t >> 2, jj = t & 3;
        uint32_t* p4 = &Vsm[(t*42 + 4)*4];
        p4[0] = pack_h2(cntS[ch*16 + 2*jj],     cntS[ch*16 + 2*jj + 1]);
        p4[1] = pack_h2(cntS[ch*16 + 8 + 2*jj], cntS[ch*16 + 8 + 2*jj + 1]);
    }
    if (t < KC/2) {
        uint32_t m = 0;
        if (!(cntS[2*t]     > 0.f)) m |= 0xFC00u;
        if (!(cntS[2*t + 1] > 0.f)) m |= 0xFC00u << 16;
        mskS[t] = m;
    }
    __syncthreads();

    const uint4* CB4 = (const uint4*)Cbs;
    const uint4* VB  = (const uint4*)Vsm;

    for (int q0 = 0; q0 < Lq; q0 += NTHREADS) {
        uint4 cbA0 = CB4[(g*4 + j)*3 + 0];
        uint4 cbA1 = CB4[(g*4 + j)*3 + 1];
        uint4 cbB0 = CB4[((8+g)*4 + j)*3 + 0];
        uint4 cbB1 = CB4[((8+g)*4 + j)*3 + 1];

        uint32_t AT0[4], AT1[4];
        {
            const float* qr0 = q + (size_t)(b * Lq + q0 + w * 32 + g) * CDIM + h * D;
            const float* qr8 = qr0 + 8 * CDIM;
            uint32_t qa[4][4];
            #pragma unroll
            for (int kc = 0; kc < 4; kc++) {
                float2 x0 = *(const float2*)(qr0 + kc*16 + 2*j);
                float2 x1 = *(const float2*)(qr8 + kc*16 + 2*j);
                float2 x2 = *(const float2*)(qr0 + kc*16 + 8 + 2*j);
                float2 x3 = *(const float2*)(qr8 + kc*16 + 8 + 2*j);
                qa[kc][0] = pack_h2(x0.x, x0.y);
                qa[kc][1] = pack_h2(x1.x, x1.y);
                qa[kc][2] = pack_h2(x2.x, x2.y);
                qa[kc][3] = pack_h2(x3.x, x3.y);
            }
            float Tlo[4] = {0.f,0.f,0.f,0.f}, Thi[4] = {0.f,0.f,0.f,0.f};
            mma_f16(Tlo, qa[0], cbA0.x, cbA0.y);
            mma_f16(Tlo, qa[1], cbA0.z, cbA0.w);
            mma_f16(Tlo, qa[2], cbA1.x, cbA1.y);
            mma_f16(Tlo, qa[3], cbA1.z, cbA1.w);
            mma_f16(Thi, qa[0], cbB0.x, cbB0.y);
            mma_f16(Thi, qa[1], cbB0.z, cbB0.w);
            mma_f16(Thi, qa[2], cbB1.x, cbB1.y);
            mma_f16(Thi, qa[3], cbB1.z, cbB1.w);
            AT0[0] = pack_h2(Tlo[0], Tlo[1]);
            AT0[1] = pack_h2(Tlo[2], Tlo[3]);
            AT0[2] = pack_h2(Thi[0], Thi[1]);
            AT0[3] = pack_h2(Thi[2], Thi[3]);
        }
        {
            const float* qr16 = q + (size_t)(b * Lq + q0 + w * 32 + 16 + g) * CDIM + h * D;
            const float* qr24 = qr16 + 8 * CDIM;
            uint32_t qa[4][4];
            #pragma unroll
            for (int kc = 0; kc < 4; kc++) {
                float2 x0 = *(const float2*)(qr16 + kc*16 + 2*j);
                float2 x1 = *(const float2*)(qr24 + kc*16 + 2*j);
                float2 x2 = *(const float2*)(qr16 + kc*16 + 8 + 2*j);
                float2 x3 = *(const float2*)(qr24 + kc*16 + 8 + 2*j);
                qa[kc][0] = pack_h2(x0.x, x0.y);
                qa[kc][1] = pack_h2(x1.x, x1.y);
                qa[kc][2] = pack_h2(x2.x, x2.y);
                qa[kc][3] = pack_h2(x3.x, x3.y);
            }
            float Tlo[4] = {0.f,0.f,0.f,0.f}, Thi[4] = {0.f,0.f,0.f,0.f};
            mma_f16(Tlo, qa[0], cbA0.x, cbA0.y);
            mma_f16(Tlo, qa[1], cbA0.z, cbA0.w);
            mma_f16(Tlo, qa[2], cbA1.x, cbA1.y);
            mma_f16(Tlo, qa[3], cbA1.z, cbA1.w);
            mma_f16(Thi, qa[0], cbB0.x, cbB0.y);
            mma_f16(Thi, qa[1], cbB0.z, cbB0.w);
            mma_f16(Thi, qa[2], cbB1.x, cbB1.y);
            mma_f16(Thi, qa[3], cbB1.z, cbB1.w);
            AT1[0] = pack_h2(Tlo[0], Tlo[1]);
            AT1[1] = pack_h2(Tlo[2], Tlo[3]);
            AT1[2] = pack_h2(Thi[0], Thi[1]);
            AT1[3] = pack_h2(Thi[2], Thi[3]);
        }

        float O0[8][4], O1[8][4];
        #pragma unroll
        for (int nb = 0; nb < 8; nb++) {
            O0[nb][0]=0.f; O0[nb][1]=0.f; O0[nb][2]=0.f; O0[nb][3]=0.f;
            O1[nb][0]=0.f; O1[nb][1]=0.f; O1[nb][2]=0.f; O1[nb][3]=0.f;
        }
        float O8a[4] = {0.f,0.f,0.f,0.f}, O8b[4] = {0.f,0.f,0.f,0.f};

        #pragma unroll 2
        for (int ch = 0; ch < 16; ch++) {
            uint2 ba = BA2[(ch*16 + g)*4 + j];
            uint2 bb = BA2[(ch*16 + 8 + g)*4 + j];
            uint32_t mlo = mskS[ch*8 + j], mhi = mskS[ch*8 + 4 + j];

            uint32_t A0[4];
            {
                float slo[4] = {0.f,0.f,0.f,0.f}, shi[4] = {0.f,0.f,0.f,0.f};
                mma_f16(slo, AT0, ba.x, ba.y);
                mma_f16(shi, AT0, bb.x, bb.y);
                A0[0] = ex2_h2(hadd2_u(pack_h2(slo[0], slo[1]), mlo));
                A0[1] = ex2_h2(hadd2_u(pack_h2(slo[2], slo[3]), mlo));
                A0[2] = ex2_h2(hadd2_u(pack_h2(shi[0], shi[1]), mhi));
                A0[3] = ex2_h2(hadd2_u(pack_h2(shi[2], shi[3]), mhi));
            }
            uint32_t A1[4];
            {
                float slo[4] = {0.f,0.f,0.f,0.f}, shi[4] = {0.f,0.f,0.f,0.f};
                mma_f16(slo, AT1, ba.x, ba.y);
                mma_f16(shi, AT1, bb.x, bb.y);
                A1[0] = ex2_h2(hadd2_u(pack_h2(slo[0], slo[1]), mlo));
                A1[1] = ex2_h2(hadd2_u(pack_h2(slo[2], slo[3]), mlo));
                A1[2] = ex2_h2(hadd2_u(pack_h2(shi[0], shi[1]), mhi));
                A1[3] = ex2_h2(hadd2_u(pack_h2(shi[2], shi[3]), mhi));
            }

            const uint4* vrow = VB + (ch*4 + j)*42 + g*5;
            #pragma unroll
            for (int s = 0; s < 4; s++) {
                uint4 vv = vrow[s];
                mma_f16(O0[2*s],     A0, vv.x, vv.y);
                mma_f16(O0[2*s + 1], A0, vv.z, vv.w);
                mma_f16(O1[2*s],     A1, vv.x, vv.y);
                mma_f16(O1[2*s + 1], A1, vv.z, vv.w);
            }
            uint2 vc = *(const uint2*)(vrow + 4);
            mma_f16(O8a, A0, vc.x, vc.y);
            mma_f16(O8b, A1, vc.x, vc.y);
        }

        int src = lane & 28;
        float d00 = __shfl_sync(0xffffffffu, O8a[0], src);
        float d01 = __shfl_sync(0xffffffffu, O8a[2], src);
        float d10 = __shfl_sync(0xffffffffu, O8b[0], src);
        float d11 = __shfl_sync(0xffffffffu, O8b[2], src);
        float i00 = 1.0f / d00, i01 = 1.0f / d01;
        float i10 = 1.0f / d10, i11 = 1.0f / d11;

        float* ob0  = out + (size_t)(b * Lq + q0 + w * 32 + g) * CDIM + h * D;
        float* ob8  = ob0 + 8  * CDIM;
        float* ob16 = ob0 + 16 * CDIM;
        float* ob24 = ob0 + 24 * CDIM;
        #pragma unroll
        for (int nbk = 0; nbk < 8; nbk++) {
            *(float2*)(ob0  + nbk*8 + 2*j) = make_float2(O0[nbk][0]*i00, O0[nbk][1]*i00);
            *(float2*)(ob8  + nbk*8 + 2*j) = make_float2(O0[nbk][2]*i01, O0[nbk][3]*i01);
            *(float2*)(ob16 + nbk*8 + 2*j) = make_float2(O1[nbk][0]*i10, O1[nbk][1]*i10);
            *(float2*)(ob24 + nbk*8 + 2*j) = make_float2(O1[nbk][2]*i11, O1[nbk][3]*i11);
        }
    }
}

// ---------------- launch ----------------
extern "C" void kernel_launch(void* const* d_in, const int* in_sizes, int n_in,
                              void* d_out, int out_size)
{
    const float* q  = (const float*)d_in[0];
    const float* k  = (const float*)d_in[1];
    const float* v  = (const float*)d_in[2];
    const float* Wc = (const float*)d_in[3];
    const float* bc = (const float*)d_in[4];
    const float* cb = (const float*)d_in[5];

    int B    = in_sizes[6];
    int C    = in_sizes[3] / CS;
    int Lk   = in_sizes[1] / (B * C);
    int Lq   = in_sizes[0] / (B * C);
    int nTok = B * Lk;
    (void)n_in; (void)out_size;

    idx_kernel<<<(nTok + 31) / 32, 256>>>(k, Wc, bc, Lk, nTok);
    gather_kernel<<<B * KC, 256>>>(v, Lk);

    cudaFuncSetAttribute(attn_kernel,
                         cudaFuncAttributeMaxDynamicSharedMemorySize, SM_TOT);
    dim3 grid(NH, B);
    attn_kernel<<<grid, NTHREADS, SM_TOT>>>(q, cb, (float*)d_out, Lq);
}

// round 17
// speedup vs baseline: 1.1960x; 1.0882x over previous
#include <cuda_runtime.h>
#include <cuda_fp16.h>
#include <math.h>
#include <stdint.h>

#define CS    8
#define KC    256
#define NH    16
#define D     64
#define CDIM  1024
#define MAXB  8
#define MAXLK 4096
#define MAXTOK (MAXB*MAXLK)

typedef unsigned long long ull;

// ---------------- device scratch ----------------
__device__ int   g_idx[MAXTOK];
__device__ int   g_counts[MAXB*KC];
__device__ float g_codv[MAXB*KC*CDIM];          // [b][bucket][C]  8 MB

// ---------------- helpers ----------------
__device__ __forceinline__ uint32_t pack_h2(float a, float b) {
    __half2 h = __floats2half2_rn(a, b);
    return *(uint32_t*)&h;
}
__device__ __forceinline__ uint32_t hadd2_u(uint32_t a, uint32_t b) {
    __half2 r = __hadd2(*(__half2*)&a, *(__half2*)&b);
    return *(uint32_t*)&r;
}
__device__ __forceinline__ uint32_t ex2_h2(uint32_t x) {
    uint32_t r; asm("ex2.approx.f16x2 %0, %1;" : "=r"(r) : "r"(x)); return r;
}
__device__ __forceinline__ uint32_t prmt_u(uint32_t a, uint32_t b, uint32_t sel) {
    uint32_t r; asm("prmt.b32 %0, %1, %2, %3;" : "=r"(r) : "r"(a), "r"(b), "r"(sel));
    return r;
}
__device__ __forceinline__ void mma_f16(float c[4], const uint32_t a[4],
                                        uint32_t b0, uint32_t b1) {
    asm volatile("mma.sync.aligned.m16n8k16.row.col.f32.f16.f16.f32 "
        "{%0,%1,%2,%3}, {%4,%5,%6,%7}, {%8,%9}, {%0,%1,%2,%3};"
        : "+f"(c[0]), "+f"(c[1]), "+f"(c[2]), "+f"(c[3])
        : "r"(a[0]), "r"(a[1]), "r"(a[2]), "r"(a[3]), "r"(b0), "r"(b1));
}
// ---- packed fp32x2 (Blackwell, base sm_100+ PTX) ----
__device__ __forceinline__ ull pack2(float a, float b) {
    ull r; asm("mov.b64 %0, {%1, %2};" : "=l"(r) : "f"(a), "f"(b)); return r;
}
__device__ __forceinline__ ull dup2(float a) {
    ull r; asm("mov.b64 %0, {%1, %1};" : "=l"(r) : "f"(a)); return r;
}
__device__ __forceinline__ void fma2(ull& c, ull a, ull b) {
    asm("fma.rn.f32x2 %0, %1, %2, %0;" : "+l"(c) : "l"(a), "l"(b));
}
__device__ __forceinline__ float2 unpack2(ull v) {
    float2 f; asm("mov.b64 {%0, %1}, %2;" : "=f"(f.x), "=f"(f.y) : "l"(v)); return f;
}

// ---------------- K1: bucket index (persistent, packed f32x2 dots) ----------------
// 296 blocks grid-stride over 4-row warp-groups. Wc packed once per block into
// paired layout: sWa[jp*256+i] = {{w_{2jp},w_{2jp+1}} for elems 0,1}, sWb = elems 2,3.
// Per iter: 4 LDG.128 + 8 LDS.128 (conflict-free, 16B stride) + 16 dup + 64 FFMA2.
// Per-half arithmetic identical to scalar chain -> codes bit-identical to R16.
#define IDX_GRID 296
__global__ void __launch_bounds__(256, 2) idx_kernel(
    const float* __restrict__ k, const float* __restrict__ Wc,
    const float* __restrict__ bc, int Lk, int nTok)
{
    __shared__ ulonglong2 sWa[4*256];   // 16 KB
    __shared__ ulonglong2 sWb[4*256];   // 16 KB
    __shared__ float sbc[CS];
    int t = threadIdx.x;
    for (int idx = t; idx < 1024; idx += 256) {
        int jp = idx >> 8, i = idx & 255;
        const float* w0 = Wc + (size_t)(2*jp)     * CDIM + i * 4;
        const float* w1 = Wc + (size_t)(2*jp + 1) * CDIM + i * 4;
        sWa[idx] = make_ulonglong2(pack2(w0[0], w1[0]), pack2(w0[1], w1[1]));
        sWb[idx] = make_ulonglong2(pack2(w0[2], w1[2]), pack2(w0[3], w1[3]));
    }
    if (t < CS) sbc[t] = bc[t];
    __syncthreads();

    int warp = t >> 5, lane = t & 31;
    for (int grp = blockIdx.x * 8 + warp; grp * 4 < nTok; grp += IDX_GRID * 8) {
        int rowBase = grp * 4;
        const float4* kbase = (const float4*)(k + (size_t)rowBase * CDIM);

        ull acc2[4][4];
        #pragma unroll
        for (int r = 0; r < 4; r++)
            #pragma unroll
            for (int jp = 0; jp < 4; jp++) acc2[r][jp] = 0ULL;

        for (int i = lane; i < CDIM/4; i += 32) {
            ull kd[4][4];
            #pragma unroll
            for (int r = 0; r < 4; r++) {
                float4 kv = kbase[(size_t)r * (CDIM/4) + i];
                kd[r][0] = dup2(kv.x); kd[r][1] = dup2(kv.y);
                kd[r][2] = dup2(kv.z); kd[r][3] = dup2(kv.w);
            }
            #pragma unroll
            for (int jp = 0; jp < 4; jp++) {
                ulonglong2 wa = sWa[jp*256 + i];
                ulonglong2 wb = sWb[jp*256 + i];
                #pragma unroll
                for (int r = 0; r < 4; r++) {
                    fma2(acc2[r][jp], kd[r][0], wa.x);
                    fma2(acc2[r][jp], kd[r][1], wa.y);
                    fma2(acc2[r][jp], kd[r][2], wb.x);
                    fma2(acc2[r][jp], kd[r][3], wb.y);
                }
            }
        }

        float acc[4][8];
        #pragma unroll
        for (int r = 0; r < 4; r++)
            #pragma unroll
            for (int jp = 0; jp < 4; jp++) {
                float2 p = unpack2(acc2[r][jp]);
                acc[r][2*jp]     = p.x;
                acc[r][2*jp + 1] = p.y;
            }
        #pragma unroll
        for (int r = 0; r < 4; r++) {
            #pragma unroll
            for (int j = 0; j < CS; j++) {
                #pragma unroll
                for (int o = 16; o >= 1; o >>= 1)
                    acc[r][j] += __shfl_xor_sync(0xffffffffu, acc[r][j], o);
            }
            if (lane == 0) {
                int code = 0;
                #pragma unroll
                for (int j = 0; j < CS; j++)
                    if (acc[r][j] + sbc[j] >= 0.f) code |= (1 << (7 - j));
                g_idx[rowBase + r] = code;
            }
        }
    }
}

// ---------------- K5: gather-sum v per bucket (warp-local 2-pass compaction) ----
__global__ void __launch_bounds__(256) gather_kernel(const float* __restrict__ v, int Lk) {
    int bk = blockIdx.x;
    int b = bk >> 8, bucket = bk & (KC - 1);
    __shared__ int toks[MAXLK];
    __shared__ int wcnt[8];
    int t = threadIdx.x, warp = t >> 5, lane = t & 31;
    const int* idxb = g_idx + (size_t)b * Lk;
    const float* vb = v + (size_t)b * Lk * CDIM;

    const int segLen = Lk >> 3;
    const int seg = warp * segLen;
    const int nIt = segLen >> 5;
    unsigned bals[MAXLK/8/32];
    int myCnt = 0;
    for (int it = 0; it < nIt; it++) {
        bool m = (idxb[seg + it*32 + lane] == bucket);
        unsigned bal = __ballot_sync(0xffffffffu, m);
        bals[it] = bal;
        myCnt += __popc(bal);
    }
    if (lane == 0) wcnt[warp] = myCnt;
    __syncthreads();
    int off = 0, cnt = 0;
    #pragma unroll
    for (int ww = 0; ww < 8; ww++) {
        int c = wcnt[ww];
        if (ww < warp) off += c;
        cnt += c;
    }
    const unsigned lm = (1u << lane) - 1u;
    for (int it = 0; it < nIt; it++) {
        unsigned bal = bals[it];
        if (bal & (1u << lane))
            toks[off + __popc(bal & lm)] = seg + it*32 + lane;
        off += __popc(bal);
    }
    __syncthreads();

    float4 a0 = make_float4(0.f,0.f,0.f,0.f), a1 = a0, a2 = a0, a3 = a0;
    float4 a4 = a0, a5 = a0, a6 = a0, a7 = a0;
    int i = 0;
    for (; i + 8 <= cnt; i += 8) {
        float4 x0 = *(const float4*)(vb + (size_t)toks[i]     * CDIM + t * 4);
        float4 x1 = *(const float4*)(vb + (size_t)toks[i + 1] * CDIM + t * 4);
        float4 x2 = *(const float4*)(vb + (size_t)toks[i + 2] * CDIM + t * 4);
        float4 x3 = *(const float4*)(vb + (size_t)toks[i + 3] * CDIM + t * 4);
        float4 x4 = *(const float4*)(vb + (size_t)toks[i + 4] * CDIM + t * 4);
        float4 x5 = *(const float4*)(vb + (size_t)toks[i + 5] * CDIM + t * 4);
        float4 x6 = *(const float4*)(vb + (size_t)toks[i + 6] * CDIM + t * 4);
        float4 x7 = *(const float4*)(vb + (size_t)toks[i + 7] * CDIM + t * 4);
        a0.x += x0.x; a0.y += x0.y; a0.z += x0.z; a0.w += x0.w;
        a1.x += x1.x; a1.y += x1.y; a1.z += x1.z; a1.w += x1.w;
        a2.x += x2.x; a2.y += x2.y; a2.z += x2.z; a2.w += x2.w;
        a3.x += x3.x; a3.y += x3.y; a3.z += x3.z; a3.w += x3.w;
        a4.x += x4.x; a4.y += x4.y; a4.z += x4.z; a4.w += x4.w;
        a5.x += x5.x; a5.y += x5.y; a5.z += x5.z; a5.w += x5.w;
        a6.x += x6.x; a6.y += x6.y; a6.z += x6.z; a6.w += x6.w;
        a7.x += x7.x; a7.y += x7.y; a7.z += x7.z; a7.w += x7.w;
    }
    for (; i < cnt; i++) {
        float4 x0 = *(const float4*)(vb + (size_t)toks[i] * CDIM + t * 4);
        a0.x += x0.x; a0.y += x0.y; a0.z += x0.z; a0.w += x0.w;
    }
    float4 acc;
    acc.x = ((a0.x + a1.x) + (a2.x + a3.x)) + ((a4.x + a5.x) + (a6.x + a7.x));
    acc.y = ((a0.y + a1.y) + (a2.y + a3.y)) + ((a4.y + a5.y) + (a6.y + a7.y));
    acc.z = ((a0.z + a1.z) + (a2.z + a3.z)) + ((a4.z + a5.z) + (a6.z + a7.z));
    acc.w = ((a0.w + a1.w) + (a2.w + a3.w)) + ((a4.w + a5.w) + (a6.w + a7.w));
    *(float4*)(g_codv + (size_t)bk * CDIM + t * 4) = acc;
    if (t == 0) g_counts[bk] = cnt;
}

// ---------------- K6: low-rank fp16 attention, 512 threads, M=32/warp ----------------
// (unchanged: 49.6us, ~85% of its HMMA floor)
#define NTHREADS 512
#define CB_OFF  0
#define BA_OFF  3072
#define V_OFF   11264
#define CNT_OFF 54272
#define MSK_OFF 55296
#define VST_OFF 55808
#define SM_TOT  (VST_OFF + KC*D*2)     // 88576

__global__ void __launch_bounds__(NTHREADS, 1) attn_kernel(
    const float* __restrict__ q, const float* __restrict__ cb,
    float* __restrict__ out, int Lq)
{
    extern __shared__ char sm[];
    uint32_t* Cbs  = (uint32_t*)(sm + CB_OFF);
    uint2*    BA2  = (uint2*)   (sm + BA_OFF);
    uint32_t* Vsm  = (uint32_t*)(sm + V_OFF);
    float*    cntS = (float*)   (sm + CNT_OFF);
    uint32_t* mskS = (uint32_t*)(sm + MSK_OFF);
    uint32_t* Vst  = (uint32_t*)(sm + VST_OFF);

    const int t = threadIdx.x, lane = t & 31, w = t >> 5;
    const int h = blockIdx.x, b = blockIdx.y;
    const int j = lane & 3, g = lane >> 2;
    const float QS = 0.125f * 1.4426950408889634f;

    {
        int s = t;
        int n = s >> 5, p = s & 31;
        const float* src = cb + (size_t)n * CDIM + h * D + 2 * p;
        float2 x = make_float2(src[0] * QS, src[1] * QS);
        int jj = p & 3, qq = p >> 2;
        int kc = qq >> 1, ww = qq & 1;
        int slot = kc >> 1, c = ((kc & 1) << 1) | ww;
        Cbs[((n*4 + jj)*3 + slot)*4 + c] = pack_h2(x.x, x.y);
    }
    #pragma unroll
    for (int i = 0; i < 2; i++) {
        int s = t + NTHREADS * i;
        int n = s >> 2, jj = s & 3;
        float b0a = (float)((n >> (7 - 2*jj)) & 1);
        float b0b = (float)((n >> (7 - (2*jj+1))) & 1);
        BA2[n*4 + jj] = make_uint2(pack_h2(b0a, b0b),
                                   pack_h2(1.f - b0a, 1.f - b0b));
    }
    {
        int i = t;
        int row = i >> 3, gg = i & 7;
        uint32_t* p4 = &Vsm[(row*42 + gg*5 + 4)*4];
        p4[0] = 0; p4[1] = 0; p4[2] = 0; p4[3] = 0;
    }
    {
        const float4* vsrc = (const float4*)(g_codv + ((size_t)b * KC) * CDIM + h * D);
        uint2* vst2 = (uint2*)Vst;
        #pragma unroll
        for (int i = 0; i < 8; i++) {
            int s = t + NTHREADS * i;
            int n = s >> 4, c4 = s & 15;
            float4 x = vsrc[(size_t)n * (CDIM/4) + c4];
            vst2[n * 16 + c4] = make_uint2(pack_h2(x.x, x.y), pack_h2(x.z, x.w));
        }
    }
    if (t < KC) cntS[t] = (float)g_counts[b * KC + t];
    __syncthreads();

    #pragma unroll
    for (int i = 0; i < 8; i++) {
        int s = t + NTHREADS * i;
        int d2 = s & 31, p = s >> 5;
        uint32_t a  = Vst[(2*p)     * 32 + d2];
        uint32_t b2 = Vst[(2*p + 1) * 32 + d2];
        uint32_t lo = prmt_u(a, b2, 0x5410);
        uint32_t hi = prmt_u(a, b2, 0x7632);
        int ch = p >> 3, r = p & 7;
        int jj = r & 3, ww = r >> 2;
        #pragma unroll
        for (int e = 0; e < 2; e++) {
            int d = 2*d2 + e;
            uint32_t val = e ? hi : lo;
            int nbk = d >> 3, gg = d & 7;
            int slot = nbk >> 1, c = ((nbk & 1) << 1) | ww;
            Vsm[(((ch*4 + jj)*42) + gg*5 + slot)*4 + c] = val;
        }
    }
    if (t < 64) {
        int ch = t >> 2, jj = t & 3;
        uint32_t* p4 = &Vsm[(t*42 + 4)*4];
        p4[0] = pack_h2(cntS[ch*16 + 2*jj],     cntS[ch*16 + 2*jj + 1]);
        p4[1] = pack_h2(cntS[ch*16 + 8 + 2*jj], cntS[ch*16 + 8 + 2*jj + 1]);
    }
    if (t < KC/2) {
        uint32_t m = 0;
        if (!(cntS[2*t]     > 0.f)) m |= 0xFC00u;
        if (!(cntS[2*t + 1] > 0.f)) m |= 0xFC00u << 16;
        mskS[t] = m;
    }
    __syncthreads();

    const uint4* CB4 = (const uint4*)Cbs;
    const uint4* VB  = (const uint4*)Vsm;

    for (int q0 = 0; q0 < Lq; q0 += NTHREADS) {
        uint4 cbA0 = CB4[(g*4 + j)*3 + 0];
        uint4 cbA1 = CB4[(g*4 + j)*3 + 1];
        uint4 cbB0 = CB4[((8+g)*4 + j)*3 + 0];
        uint4 cbB1 = CB4[((8+g)*4 + j)*3 + 1];

        uint32_t AT0[4], AT1[4];
        {
            const float* qr0 = q + (size_t)(b * Lq + q0 + w * 32 + g) * CDIM + h * D;
            const float* qr8 = qr0 + 8 * CDIM;
            uint32_t qa[4][4];
            #pragma unroll
            for (int kc = 0; kc < 4; kc++) {
                float2 x0 = *(const float2*)(qr0 + kc*16 + 2*j);
                float2 x1 = *(const float2*)(qr8 + kc*16 + 2*j);
                float2 x2 = *(const float2*)(qr0 + kc*16 + 8 + 2*j);
                float2 x3 = *(const float2*)(qr8 + kc*16 + 8 + 2*j);
                qa[kc][0] = pack_h2(x0.x, x0.y);
                qa[kc][1] = pack_h2(x1.x, x1.y);
                qa[kc][2] = pack_h2(x2.x, x2.y);
                qa[kc][3] = pack_h2(x3.x, x3.y);
            }
            float Tlo[4] = {0.f,0.f,0.f,0.f}, Thi[4] = {0.f,0.f,0.f,0.f};
            mma_f16(Tlo, qa[0], cbA0.x, cbA0.y);
            mma_f16(Tlo, qa[1], cbA0.z, cbA0.w);
            mma_f16(Tlo, qa[2], cbA1.x, cbA1.y);
            mma_f16(Tlo, qa[3], cbA1.z, cbA1.w);
            mma_f16(Thi, qa[0], cbB0.x, cbB0.y);
            mma_f16(Thi, qa[1], cbB0.z, cbB0.w);
            mma_f16(Thi, qa[2], cbB1.x, cbB1.y);
            mma_f16(Thi, qa[3], cbB1.z, cbB1.w);
            AT0[0] = pack_h2(Tlo[0], Tlo[1]);
            AT0[1] = pack_h2(Tlo[2], Tlo[3]);
            AT0[2] = pack_h2(Thi[0], Thi[1]);
            AT0[3] = pack_h2(Thi[2], Thi[3]);
        }
        {
            const float* qr16 = q + (size_t)(b * Lq + q0 + w * 32 + 16 + g) * CDIM + h * D;
            const float* qr24 = qr16 + 8 * CDIM;
            uint32_t qa[4][4];
            #pragma unroll
            for (int kc = 0; kc < 4; kc++) {
                float2 x0 = *(const float2*)(qr16 + kc*16 + 2*j);
                float2 x1 = *(const float2*)(qr24 + kc*16 + 2*j);
                float2 x2 = *(const float2*)(qr16 + kc*16 + 8 + 2*j);
                float2 x3 = *(const float2*)(qr24 + kc*16 + 8 + 2*j);
                qa[kc][0] = pack_h2(x0.x, x0.y);
                qa[kc][1] = pack_h2(x1.x, x1.y);
                qa[kc][2] = pack_h2(x2.x, x2.y);
                qa[kc][3] = pack_h2(x3.x, x3.y);
            }
            float Tlo[4] = {0.f,0.f,0.f,0.f}, Thi[4] = {0.f,0.f,0.f,0.f};
            mma_f16(Tlo, qa[0], cbA0.x, cbA0.y);
            mma_f16(Tlo, qa[1], cbA0.z, cbA0.w);
            mma_f16(Tlo, qa[2], cbA1.x, cbA1.y);
            mma_f16(Tlo, qa[3], cbA1.z, cbA1.w);
            mma_f16(Thi, qa[0], cbB0.x, cbB0.y);
            mma_f16(Thi, qa[1], cbB0.z, cbB0.w);
            mma_f16(Thi, qa[2], cbB1.x, cbB1.y);
            mma_f16(Thi, qa[3], cbB1.z, cbB1.w);
            AT1[0] = pack_h2(Tlo[0], Tlo[1]);
            AT1[1] = pack_h2(Tlo[2], Tlo[3]);
            AT1[2] = pack_h2(Thi[0], Thi[1]);
            AT1[3] = pack_h2(Thi[2], Thi[3]);
        }

        float O0[8][4], O1[8][4];
        #pragma unroll
        for (int nb = 0; nb < 8; nb++) {
            O0[nb][0]=0.f; O0[nb][1]=0.f; O0[nb][2]=0.f; O0[nb][3]=0.f;
            O1[nb][0]=0.f; O1[nb][1]=0.f; O1[nb][2]=0.f; O1[nb][3]=0.f;
        }
        float O8a[4] = {0.f,0.f,0.f,0.f}, O8b[4] = {0.f,0.f,0.f,0.f};

        #pragma unroll 2
        for (int ch = 0; ch < 16; ch++) {
            uint2 ba = BA2[(ch*16 + g)*4 + j];
            uint2 bb = BA2[(ch*16 + 8 + g)*4 + j];
            uint32_t mlo = mskS[ch*8 + j], mhi = mskS[ch*8 + 4 + j];

            uint32_t A0[4];
            {
                float slo[4] = {0.f,0.f,0.f,0.f}, shi[4] = {0.f,0.f,0.f,0.f};
                mma_f16(slo, AT0, ba.x, ba.y);
                mma_f16(shi, AT0, bb.x, bb.y);
                A0[0] = ex2_h2(hadd2_u(pack_h2(slo[0], slo[1]), mlo));
                A0[1] = ex2_h2(hadd2_u(pack_h2(slo[2], slo[3]), mlo));
                A0[2] = ex2_h2(hadd2_u(pack_h2(shi[0], shi[1]), mhi));
                A0[3] = ex2_h2(hadd2_u(pack_h2(shi[2], shi[3]), mhi));
            }
            uint32_t A1[4];
            {
                float slo[4] = {0.f,0.f,0.f,0.f}, shi[4] = {0.f,0.f,0.f,0.f};
                mma_f16(slo, AT1, ba.x, ba.y);
                mma_f16(shi, AT1, bb.x, bb.y);
                A1[0] = ex2_h2(hadd2_u(pack_h2(slo[0], slo[1]), mlo));
                A1[1] = ex2_h2(hadd2_u(pack_h2(slo[2], slo[3]), mlo));
                A1[2] = ex2_h2(hadd2_u(pack_h2(shi[0], shi[1]), mhi));
                A1[3] = ex2_h2(hadd2_u(pack_h2(shi[2], shi[3]), mhi));
            }

            const uint4* vrow = VB + (ch*4 + j)*42 + g*5;
            #pragma unroll
            for (int s = 0; s < 4; s++) {
                uint4 vv = vrow[s];
                mma_f16(O0[2*s],     A0, vv.x, vv.y);
                mma_f16(O0[2*s + 1], A0, vv.z, vv.w);
                mma_f16(O1[2*s],     A1, vv.x, vv.y);
                mma_f16(O1[2*s + 1], A1, vv.z, vv.w);
            }
            uint2 vc = *(const uint2*)(vrow + 4);
            mma_f16(O8a, A0, vc.x, vc.y);
            mma_f16(O8b, A1, vc.x, vc.y);
        }

        int src = lane & 28;
        float d00 = __shfl_sync(0xffffffffu, O8a[0], src);
        float d01 = __shfl_sync(0xffffffffu, O8a[2], src);
        float d10 = __shfl_sync(0xffffffffu, O8b[0], src);
        float d11 = __shfl_sync(0xffffffffu, O8b[2], src);
        float i00 = 1.0f / d00, i01 = 1.0f / d01;
        float i10 = 1.0f / d10, i11 = 1.0f / d11;

        float* ob0  = out + (size_t)(b * Lq + q0 + w * 32 + g) * CDIM + h * D;
        float* ob8  = ob0 + 8  * CDIM;
        float* ob16 = ob0 + 16 * CDIM;
        float* ob24 = ob0 + 24 * CDIM;
        #pragma unroll
        for (int nbk = 0; nbk < 8; nbk++) {
            *(float2*)(ob0  + nbk*8 + 2*j) = make_float2(O0[nbk][0]*i00, O0[nbk][1]*i00);
            *(float2*)(ob8  + nbk*8 + 2*j) = make_float2(O0[nbk][2]*i01, O0[nbk][3]*i01);
            *(float2*)(ob16 + nbk*8 + 2*j) = make_float2(O1[nbk][0]*i10, O1[nbk][1]*i10);
            *(float2*)(ob24 + nbk*8 + 2*j) = make_float2(O1[nbk][2]*i11, O1[nbk][3]*i11);
        }
    }
}

// ---------------- launch ----------------
extern "C" void kernel_launch(void* const* d_in, const int* in_sizes, int n_in,
                              void* d_out, int out_size)
{
    const float* q  = (const float*)d_in[0];
    const float* k  = (const float*)d_in[1];
    const float* v  = (const float*)d_in[2];
    const float* Wc = (const float*)d_in[3];
    const float* bc = (const float*)d_in[4];
    const float* cb = (const float*)d_in[5];

    int B    = in_sizes[6];
    int C    = in_sizes[3] / CS;
    int Lk   = in_sizes[1] / (B * C);
    int Lq   = in_sizes[0] / (B * C);
    int nTok = B * Lk;
    (void)n_in; (void)out_size;

    idx_kernel<<<IDX_GRID, 256>>>(k, Wc, bc, Lk, nTok);
    gather_kernel<<<B * KC, 256>>>(v, Lk);

    cudaFuncSetAttribute(attn_kernel,
                         cudaFuncAttributeMaxDynamicSharedMemorySize, SM_TOT);
    dim3 grid(NH, B);
    attn_kernel<<<grid, NTHREADS, SM_TOT>>>(q, cb, (float*)d_out, Lq);
}